// round 2
// baseline (speedup 1.0000x reference)
#include <cuda_runtime.h>

#define KCLS 19
#define Bn 4
#define Cn 64
#define HWn 262144      // 512*512
#define EPSf 1e-5f
#define COUNTf 6.0f

#define TP 128          // pixels per stats tile
#define BLKS_PER_B 74   // stats blocks per batch image
#define NBLK (Bn * BLKS_PER_B)   // 296
#define BKC (KCLS * Cn)          // 1216

#define TA 1024         // pixels per apply block

// ---- deterministic per-block partial scratch (no atomics anywhere) ----
__device__ float g_s1p[NBLK * BKC];
__device__ float g_s2p[NBLK * BKC];
__device__ float g_cntp[NBLK * KCLS];
__device__ float2 g_comb[Bn * BKC];   // (scale, shift) per (b,k,c)

// ============================================================================
// Kernel 1: per-(b,k,c) sum / sumsq via warp-uniform-class register binning.
// Block = 256 threads, 8 warps. Each warp processes one pixel at a time across
// all 64 channels (lane -> channels {lane, lane+32}), so the class label is
// warp-uniform and the 19-way switch is non-divergent and register-indexed.
// ============================================================================
__global__ __launch_bounds__(256, 2) void stats_kernel(
    const float* __restrict__ x, const int* __restrict__ y)
{
    __shared__ float xs[64 * TP];     // bank-rotated tile: xs[c*TP + ((p+c)&127)]
    __shared__ int   ls[TP];
    __shared__ float msum[BKC];
    __shared__ float msq[BKC];
    __shared__ float scnt[KCLS];

    const int tid  = threadIdx.x;
    const int lane = tid & 31;
    const int w    = tid >> 5;
    const int b    = blockIdx.x / BLKS_PER_B;
    const int blk  = blockIdx.x % BLKS_PER_B;

    const float* xb = x + (size_t)b * Cn * HWn;
    const int*   yb = y + (size_t)b * HWn;

    float S0[KCLS], Q0[KCLS], S1[KCLS], Q1[KCLS];
#pragma unroll
    for (int j = 0; j < KCLS; j++) { S0[j]=0.f; Q0[j]=0.f; S1[j]=0.f; Q1[j]=0.f; }
    float myCnt = 0.f;   // lane j (<19) owns the count of class j for this warp

    const int ntiles = HWn / TP;      // 2048 per batch
    for (int tile = blk; tile < ntiles; tile += BLKS_PER_B) {
        const int p0 = tile * TP;
        if (tid < TP) ls[tid] = yb[p0 + tid];
        // load 64x128 floats = 2048 float4, 8 per thread; scalar stores with
        // per-row rotation (p + c) & 127 -> conflict-free reads later
#pragma unroll
        for (int i = 0; i < 8; i++) {
            int f = i * 256 + tid;            // 0..2047
            int c = f >> 5;                   // 32 float4 per row
            int j = f & 31;
            float4 v = *(const float4*)(xb + (size_t)c * HWn + p0 + 4 * j);
            int base = c * TP;
            int pp = 4 * j + c;
            xs[base + ( pp      & 127)] = v.x;
            xs[base + ((pp + 1) & 127)] = v.y;
            xs[base + ((pp + 2) & 127)] = v.z;
            xs[base + ((pp + 3) & 127)] = v.w;
        }
        __syncthreads();

        for (int i = 0; i < 16; i++) {
            int p = w * 16 + i;
            float v0 = xs[lane * TP + ((p + lane) & 127)];
            float v1 = xs[(lane + 32) * TP + ((p + lane + 32) & 127)];
            int k = ls[p];                    // warp-uniform
            myCnt += (k == lane) ? 1.f : 0.f;
            switch (k) {
#define CASE(j) case j: S0[j]+=v0; Q0[j]=fmaf(v0,v0,Q0[j]); S1[j]+=v1; Q1[j]=fmaf(v1,v1,Q1[j]); break;
                CASE(0)  CASE(1)  CASE(2)  CASE(3)  CASE(4)
                CASE(5)  CASE(6)  CASE(7)  CASE(8)  CASE(9)
                CASE(10) CASE(11) CASE(12) CASE(13) CASE(14)
                CASE(15) CASE(16) CASE(17) CASE(18)
#undef CASE
                default: break;
            }
        }
        __syncthreads();
    }

    // ---- block-level merge: serialized warp phases, no atomics ----
    for (int i = tid; i < BKC; i += 256) { msum[i] = 0.f; msq[i] = 0.f; }
    if (tid < KCLS) scnt[tid] = 0.f;
    __syncthreads();
    for (int ww = 0; ww < 8; ww++) {
        if (w == ww) {
#pragma unroll
            for (int j = 0; j < KCLS; j++) {
                msum[j * 64 + lane]      += S0[j];
                msum[j * 64 + lane + 32] += S1[j];
                msq [j * 64 + lane]      += Q0[j];
                msq [j * 64 + lane + 32] += Q1[j];
            }
            if (lane < KCLS) scnt[lane] += myCnt;
        }
        __syncthreads();
    }
    // ---- write deterministic per-block partials ----
    float* s1p = g_s1p + (size_t)blockIdx.x * BKC;
    float* s2p = g_s2p + (size_t)blockIdx.x * BKC;
    for (int i = tid; i < BKC; i += 256) { s1p[i] = msum[i]; s2p[i] = msq[i]; }
    if (tid < KCLS) g_cntp[blockIdx.x * KCLS + tid] = scnt[tid];
}

// ============================================================================
// Kernel 2: reduce partials, compute (scale, shift), write style outputs.
// grid = 76 blocks (one per (b,k)), 64 threads (one per channel).
// ============================================================================
__global__ void finalize_kernel(
    const float* __restrict__ style_means, const float* __restrict__ style_stds,
    float* __restrict__ dout)
{
    const int bk = blockIdx.x;            // 0..75
    const int c  = threadIdx.x;           // 0..63
    const int b  = bk / KCLS;
    const int k  = bk % KCLS;

    float s1 = 0.f, s2 = 0.f, cnt = 0.f;
    const int base = b * BLKS_PER_B;
    for (int blk = 0; blk < BLKS_PER_B; blk++) {
        int g = base + blk;
        s1  += g_s1p[(size_t)g * BKC + k * 64 + c];
        s2  += g_s2p[(size_t)g * BKC + k * 64 + c];
        cnt += g_cntp[g * KCLS + k];
    }
    float cs   = fmaxf(cnt, 1.f);
    float mean = s1 / cs;
    float var  = (s2 - cs * mean * mean) / fmaxf(cnt - 1.f, 1.f);
    float stdc = sqrtf(fmaxf(var, 0.f)) + EPSf;
    bool valid = cnt > COUNTf;

    float sm = style_means[k * 64 + c];
    float ss = style_stds[k * 64 + c];
    float scale = valid ? (ss / stdc) : 1.f;
    float shift = valid ? (sm - mean * scale) : 0.f;
    g_comb[bk * 64 + c] = make_float2(scale, shift);

    // output tails: style_means_1dim | style_stds_1dim | valid_bk
    float* o1 = dout + (size_t)Bn * Cn * HWn;
    float* o2 = o1 + Bn * BKC;
    float* o3 = o2 + Bn * BKC;
    o1[bk * 64 + c] = valid ? sm : 0.f;
    o2[bk * 64 + c] = valid ? ss : 0.f;
    if (c == 0) o3[bk] = valid ? 1.f : 0.f;
}

// ============================================================================
// Kernel 3: apply. out = x * scale[b,lab,c] + shift[b,lab,c].
// Labels held in registers across the channel loop; (scale,shift) float2 table
// in SMEM with stride-67 padding (gcd(3,32)=1 -> conflict-free label-indexed
// LDS.64). Pure float4 streaming otherwise.
// ============================================================================
__global__ __launch_bounds__(256) void apply_kernel(
    const float* __restrict__ x, const int* __restrict__ y,
    float* __restrict__ out)
{
    __shared__ float2 comb[KCLS * 67];

    const int tid = threadIdx.x;
    const int b   = blockIdx.x / (HWn / TA);   // HW/TA = 256 tiles per batch
    const int tIn = blockIdx.x % (HWn / TA);
    const int p0  = tIn * TA;

    for (int i = tid; i < BKC; i += 256) {
        int k = i >> 6, c = i & 63;
        comb[k * 67 + c] = g_comb[(b * KCLS + k) * 64 + c];
    }
    int4 lb = ((const int4*)(y + (size_t)b * HWn + p0))[tid];
    __syncthreads();

    const float* xb = x + (size_t)b * Cn * HWn + p0;
    float*       ob = out + (size_t)b * Cn * HWn + p0;

#pragma unroll 4
    for (int c = 0; c < Cn; c++) {
        float4 v = ((const float4*)(xb + (size_t)c * HWn))[tid];
        float2 t0 = comb[lb.x * 67 + c];
        float2 t1 = comb[lb.y * 67 + c];
        float2 t2 = comb[lb.z * 67 + c];
        float2 t3 = comb[lb.w * 67 + c];
        float4 r;
        r.x = fmaf(v.x, t0.x, t0.y);
        r.y = fmaf(v.y, t1.x, t1.y);
        r.z = fmaf(v.z, t2.x, t2.y);
        r.w = fmaf(v.w, t3.x, t3.y);
        ((float4*)(ob + (size_t)c * HWn))[tid] = r;
    }
}

// ============================================================================
extern "C" void kernel_launch(void* const* d_in, const int* in_sizes, int n_in,
                              void* d_out, int out_size)
{
    const float* x  = (const float*)d_in[0];   // x_content [4,64,512,512] f32
    const int*   y  = (const int*)d_in[1];     // y_content [4,512,512] i32
    const float* sm = (const float*)d_in[2];   // style_means [19,64] f32
    const float* ss = (const float*)d_in[3];   // style_stds  [19,64] f32
    float* out = (float*)d_out;

    stats_kernel<<<NBLK, 256>>>(x, y);
    finalize_kernel<<<Bn * KCLS, Cn>>>(sm, ss, out);
    apply_kernel<<<Bn * (HWn / TA), 256>>>(x, y, out);
}

// round 6
// speedup vs baseline: 1.0218x; 1.0218x over previous
#include <cuda_runtime.h>

#define KCLS 19
#define Bn 4
#define Cn 64
#define HWn 262144      // 512*512
#define EPSf 1e-5f
#define COUNTf 6.0f

// ---- stats decomposition: 8 slices = (batch, channel-half); 37 blocks/slice
#define BLKS_PER_SLICE 37
#define NSLICE (Bn * 2)                       // 8
#define NBLK (NSLICE * BLKS_PER_SLICE)        // 296
#define WARPS_PER_SLICE (BLKS_PER_SLICE * 8)  // 296
#define CHUNK 888                             // pixels per warp (mult of 4)
#define HKC (KCLS * 32)                       // 608 accum slots per block

#define TA 1024         // pixels per apply block

// ---- deterministic per-block partial scratch (no atomics anywhere) ----
__device__ float g_s1p[NBLK * HKC];
__device__ float g_s2p[NBLK * HKC];
__device__ float g_cntp[NBLK * KCLS];
__device__ float2 g_comb[Bn * KCLS * Cn];   // (scale, shift) per (b,k,c)

// ============================================================================
// Kernel 1: per-(b,k,c) sum / sumsq, no SMEM staging.
// Lane -> channel (half*32 + lane). Warp streams pixels sequentially: per-lane
// float4 reads from its own channel row (sequential per lane -> full sector
// use via L1), label int4 is a uniform broadcast load, so the class is
// warp-uniform and the 19-way switch bins into compile-time-indexed registers.
// ============================================================================
__global__ __launch_bounds__(256, 3) void stats_kernel(
    const float* __restrict__ x, const int* __restrict__ y)
{
    const int tid   = threadIdx.x;
    const int lane  = tid & 31;
    const int w     = tid >> 5;
    const int slice = blockIdx.x / BLKS_PER_SLICE;   // 0..7
    const int bslc  = blockIdx.x % BLKS_PER_SLICE;
    const int b     = slice >> 1;
    const int half  = slice & 1;
    const int c     = half * 32 + lane;

    const float* __restrict__ xrow = x + ((size_t)b * Cn + c) * HWn;
    const int*   __restrict__ yb   = y + (size_t)b * HWn;

    float S[KCLS], Q[KCLS];
#pragma unroll
    for (int j = 0; j < KCLS; j++) { S[j] = 0.f; Q[j] = 0.f; }
    float cntf = 0.f;     // lane j (<19) counts class j over this warp's pixels

    const int i0   = (bslc * 8 + w) * CHUNK;
    const int pend = min(i0 + CHUNK, HWn);

    for (int p = i0; p < pend; p += 4) {
        int4   lb = *(const int4*)(yb + p);       // uniform broadcast
        float4 v  = *(const float4*)(xrow + p);   // per-lane row stream
        cntf += (float)((lb.x == lane) + (lb.y == lane) +
                        (lb.z == lane) + (lb.w == lane));
#define ACC(KV, VV) switch (KV) { \
    case 0:  S[0] += VV; Q[0] = fmaf(VV,VV,Q[0]); break; \
    case 1:  S[1] += VV; Q[1] = fmaf(VV,VV,Q[1]); break; \
    case 2:  S[2] += VV; Q[2] = fmaf(VV,VV,Q[2]); break; \
    case 3:  S[3] += VV; Q[3] = fmaf(VV,VV,Q[3]); break; \
    case 4:  S[4] += VV; Q[4] = fmaf(VV,VV,Q[4]); break; \
    case 5:  S[5] += VV; Q[5] = fmaf(VV,VV,Q[5]); break; \
    case 6:  S[6] += VV; Q[6] = fmaf(VV,VV,Q[6]); break; \
    case 7:  S[7] += VV; Q[7] = fmaf(VV,VV,Q[7]); break; \
    case 8:  S[8] += VV; Q[8] = fmaf(VV,VV,Q[8]); break; \
    case 9:  S[9] += VV; Q[9] = fmaf(VV,VV,Q[9]); break; \
    case 10: S[10]+= VV; Q[10]= fmaf(VV,VV,Q[10]); break; \
    case 11: S[11]+= VV; Q[11]= fmaf(VV,VV,Q[11]); break; \
    case 12: S[12]+= VV; Q[12]= fmaf(VV,VV,Q[12]); break; \
    case 13: S[13]+= VV; Q[13]= fmaf(VV,VV,Q[13]); break; \
    case 14: S[14]+= VV; Q[14]= fmaf(VV,VV,Q[14]); break; \
    case 15: S[15]+= VV; Q[15]= fmaf(VV,VV,Q[15]); break; \
    case 16: S[16]+= VV; Q[16]= fmaf(VV,VV,Q[16]); break; \
    case 17: S[17]+= VV; Q[17]= fmaf(VV,VV,Q[17]); break; \
    case 18: S[18]+= VV; Q[18]= fmaf(VV,VV,Q[18]); break; \
    default: break; }
        ACC(lb.x, v.x)
        ACC(lb.y, v.y)
        ACC(lb.z, v.z)
        ACC(lb.w, v.w)
#undef ACC
    }

    // ---- block-level merge: serialized warp phases, no atomics ----
    __shared__ float ms[HKC];
    __shared__ float mq[HKC];
    __shared__ float sc[KCLS];
    for (int i = tid; i < HKC; i += 256) { ms[i] = 0.f; mq[i] = 0.f; }
    if (tid < KCLS) sc[tid] = 0.f;
    __syncthreads();
    for (int ww = 0; ww < 8; ww++) {
        if (w == ww) {
#pragma unroll
            for (int j = 0; j < KCLS; j++) {
                ms[j * 32 + lane] += S[j];
                mq[j * 32 + lane] += Q[j];
            }
            if (lane < KCLS) sc[lane] += cntf;
        }
        __syncthreads();
    }
    float* s1p = g_s1p + (size_t)blockIdx.x * HKC;
    float* s2p = g_s2p + (size_t)blockIdx.x * HKC;
    for (int i = tid; i < HKC; i += 256) { s1p[i] = ms[i]; s2p[i] = mq[i]; }
    if (tid < KCLS) g_cntp[blockIdx.x * KCLS + tid] = sc[tid];
}

// ============================================================================
// Kernel 2: reduce partials -> (scale, shift); write style output tails.
// grid = 76 blocks (one per (b,k)), 64 threads (one per channel).
// Counts come from the half==0 slice only (both halves saw the same pixels).
// ============================================================================
__global__ void finalize_kernel(
    const float* __restrict__ style_means, const float* __restrict__ style_stds,
    float* __restrict__ dout)
{
    const int bk = blockIdx.x;            // 0..75
    const int c  = threadIdx.x;           // 0..63
    const int b  = bk / KCLS;
    const int k  = bk % KCLS;
    const int half  = c >> 5;
    const int lanec = c & 31;

    const int gbase  = (b * 2 + half) * BLKS_PER_SLICE;  // this channel's slice
    const int g0base = (b * 2) * BLKS_PER_SLICE;         // counts slice

    float s1 = 0.f, s2 = 0.f, cnt = 0.f;
    for (int blk = 0; blk < BLKS_PER_SLICE; blk++) {
        size_t g = (size_t)(gbase + blk) * HKC + k * 32 + lanec;
        s1  += g_s1p[g];
        s2  += g_s2p[g];
        cnt += g_cntp[(g0base + blk) * KCLS + k];
    }
    float cs   = fmaxf(cnt, 1.f);
    float mean = s1 / cs;
    float var  = (s2 - cs * mean * mean) / fmaxf(cnt - 1.f, 1.f);
    float stdc = sqrtf(fmaxf(var, 0.f)) + EPSf;
    bool valid = cnt > COUNTf;

    float sm = style_means[k * 64 + c];
    float ss = style_stds[k * 64 + c];
    float scale = valid ? (ss / stdc) : 1.f;
    float shift = valid ? (sm - mean * scale) : 0.f;
    g_comb[bk * 64 + c] = make_float2(scale, shift);

    // output tails: style_means_1dim | style_stds_1dim | valid_bk
    float* o1 = dout + (size_t)Bn * Cn * HWn;
    float* o2 = o1 + Bn * KCLS * Cn;
    float* o3 = o2 + Bn * KCLS * Cn;
    o1[bk * 64 + c] = valid ? sm : 0.f;
    o2[bk * 64 + c] = valid ? ss : 0.f;
    if (c == 0) o3[bk] = valid ? 1.f : 0.f;
}

// ============================================================================
// Kernel 3: apply. out = x * scale[b,lab,c] + shift[b,lab,c].
// Labels held in registers across the channel loop; (scale,shift) float2 table
// in SMEM with stride-67 padding (conflict-free label-indexed LDS.64).
// Pure float4 streaming otherwise.
// ============================================================================
__global__ __launch_bounds__(256) void apply_kernel(
    const float* __restrict__ x, const int* __restrict__ y,
    float* __restrict__ out)
{
    __shared__ float2 comb[KCLS * 67];

    const int tid = threadIdx.x;
    const int b   = blockIdx.x / (HWn / TA);
    const int tIn = blockIdx.x % (HWn / TA);
    const int p0  = tIn * TA;

    for (int i = tid; i < KCLS * Cn; i += 256) {
        int k = i >> 6, c = i & 63;
        comb[k * 67 + c] = g_comb[(b * KCLS + k) * 64 + c];
    }
    int4 lb = ((const int4*)(y + (size_t)b * HWn + p0))[tid];
    __syncthreads();

    const float* xb = x + (size_t)b * Cn * HWn + p0;
    float*       ob = out + (size_t)b * Cn * HWn + p0;

#pragma unroll 4
    for (int c = 0; c < Cn; c++) {
        float4 v = ((const float4*)(xb + (size_t)c * HWn))[tid];
        float2 t0 = comb[lb.x * 67 + c];
        float2 t1 = comb[lb.y * 67 + c];
        float2 t2 = comb[lb.z * 67 + c];
        float2 t3 = comb[lb.w * 67 + c];
        float4 r;
        r.x = fmaf(v.x, t0.x, t0.y);
        r.y = fmaf(v.y, t1.x, t1.y);
        r.z = fmaf(v.z, t2.x, t2.y);
        r.w = fmaf(v.w, t3.x, t3.y);
        ((float4*)(ob + (size_t)c * HWn))[tid] = r;
    }
}

// ============================================================================
extern "C" void kernel_launch(void* const* d_in, const int* in_sizes, int n_in,
                              void* d_out, int out_size)
{
    const float* x  = (const float*)d_in[0];   // x_content [4,64,512,512] f32
    const int*   y  = (const int*)d_in[1];     // y_content [4,512,512] i32
    const float* sm = (const float*)d_in[2];   // style_means [19,64] f32
    const float* ss = (const float*)d_in[3];   // style_stds  [19,64] f32
    float* out = (float*)d_out;

    stats_kernel<<<NBLK, 256>>>(x, y);
    finalize_kernel<<<Bn * KCLS, Cn>>>(sm, ss, out);
    apply_kernel<<<Bn * (HWn / TA), 256>>>(x, y, out);
}

// round 8
// speedup vs baseline: 1.2128x; 1.1868x over previous
#include <cuda_runtime.h>

#define KCLS 19
#define Bn 4
#define Cn 64
#define HWn 262144      // 512*512
#define EPSf 1e-5f
#define COUNTf 6.0f

// ---- stats decomposition: 8 slices = (batch, channel-half); 74 blocks/slice
#define BLKS_PER_SLICE 74
#define NSLICE (Bn * 2)                       // 8
#define NBLK (NSLICE * BLKS_PER_SLICE)        // 592  -> 4 blocks/SM, 50% occ
#define CHUNK 444                             // pixels per warp (mult of 4)
#define HKC (KCLS * 32)                       // 608 accum slots per block

#define TA 1024         // pixels per apply block

// ---- deterministic per-block partial scratch (no atomics anywhere) ----
__device__ float g_s1p[NBLK * HKC];
__device__ float g_s2p[NBLK * HKC];
__device__ float g_cntp[NBLK * KCLS];
__device__ float2 g_comb[Bn * KCLS * Cn];   // (scale, shift) per (b,k,c)

// ============================================================================
// Kernel 1: per-(b,k,c) sum / sumsq, no SMEM staging.
// Lane -> channel (half*32 + lane). Warp streams pixels sequentially: per-lane
// float4 reads from its own channel row (sequential per lane -> full sector
// use via L1), label int4 is a uniform broadcast load, so the class is
// warp-uniform and the 19-way switch bins into compile-time-indexed registers.
// Grid sized to 4 blocks/SM so taken-branch bubbles overlap across 8 warps/SMSP.
// ============================================================================
__global__ __launch_bounds__(256, 4) void stats_kernel(
    const float* __restrict__ x, const int* __restrict__ y)
{
    const int tid   = threadIdx.x;
    const int lane  = tid & 31;
    const int w     = tid >> 5;
    const int slice = blockIdx.x / BLKS_PER_SLICE;   // 0..7
    const int bslc  = blockIdx.x % BLKS_PER_SLICE;
    const int b     = slice >> 1;
    const int half  = slice & 1;
    const int c     = half * 32 + lane;

    const float* __restrict__ xrow = x + ((size_t)b * Cn + c) * HWn;
    const int*   __restrict__ yb   = y + (size_t)b * HWn;

    float S[KCLS], Q[KCLS];
#pragma unroll
    for (int j = 0; j < KCLS; j++) { S[j] = 0.f; Q[j] = 0.f; }
    float cntf = 0.f;     // lane j (<19) counts class j over this warp's pixels

    const int i0   = (bslc * 8 + w) * CHUNK;
    const int pend = min(i0 + CHUNK, HWn);

#define ACC(KV, VV) switch (KV) { \
    case 0:  S[0] += VV; Q[0] = fmaf(VV,VV,Q[0]); break; \
    case 1:  S[1] += VV; Q[1] = fmaf(VV,VV,Q[1]); break; \
    case 2:  S[2] += VV; Q[2] = fmaf(VV,VV,Q[2]); break; \
    case 3:  S[3] += VV; Q[3] = fmaf(VV,VV,Q[3]); break; \
    case 4:  S[4] += VV; Q[4] = fmaf(VV,VV,Q[4]); break; \
    case 5:  S[5] += VV; Q[5] = fmaf(VV,VV,Q[5]); break; \
    case 6:  S[6] += VV; Q[6] = fmaf(VV,VV,Q[6]); break; \
    case 7:  S[7] += VV; Q[7] = fmaf(VV,VV,Q[7]); break; \
    case 8:  S[8] += VV; Q[8] = fmaf(VV,VV,Q[8]); break; \
    case 9:  S[9] += VV; Q[9] = fmaf(VV,VV,Q[9]); break; \
    case 10: S[10]+= VV; Q[10]= fmaf(VV,VV,Q[10]); break; \
    case 11: S[11]+= VV; Q[11]= fmaf(VV,VV,Q[11]); break; \
    case 12: S[12]+= VV; Q[12]= fmaf(VV,VV,Q[12]); break; \
    case 13: S[13]+= VV; Q[13]= fmaf(VV,VV,Q[13]); break; \
    case 14: S[14]+= VV; Q[14]= fmaf(VV,VV,Q[14]); break; \
    case 15: S[15]+= VV; Q[15]= fmaf(VV,VV,Q[15]); break; \
    case 16: S[16]+= VV; Q[16]= fmaf(VV,VV,Q[16]); break; \
    case 17: S[17]+= VV; Q[17]= fmaf(VV,VV,Q[17]); break; \
    case 18: S[18]+= VV; Q[18]= fmaf(VV,VV,Q[18]); break; \
    default: break; }

    int p = i0;
    // main loop: 8 pixels per iteration, two independent load pairs (MLP)
    for (; p + 8 <= pend; p += 8) {
        int4   lb0 = *(const int4*)(yb + p);
        int4   lb1 = *(const int4*)(yb + p + 4);
        float4 v0  = *(const float4*)(xrow + p);
        float4 v1  = *(const float4*)(xrow + p + 4);
        cntf += (float)((lb0.x == lane) + (lb0.y == lane) +
                        (lb0.z == lane) + (lb0.w == lane) +
                        (lb1.x == lane) + (lb1.y == lane) +
                        (lb1.z == lane) + (lb1.w == lane));
        ACC(lb0.x, v0.x)  ACC(lb0.y, v0.y)  ACC(lb0.z, v0.z)  ACC(lb0.w, v0.w)
        ACC(lb1.x, v1.x)  ACC(lb1.y, v1.y)  ACC(lb1.z, v1.z)  ACC(lb1.w, v1.w)
    }
    for (; p < pend; p += 4) {
        int4   lb = *(const int4*)(yb + p);
        float4 v  = *(const float4*)(xrow + p);
        cntf += (float)((lb.x == lane) + (lb.y == lane) +
                        (lb.z == lane) + (lb.w == lane));
        ACC(lb.x, v.x)  ACC(lb.y, v.y)  ACC(lb.z, v.z)  ACC(lb.w, v.w)
    }
#undef ACC

    // ---- block-level merge: serialized warp phases, no atomics ----
    __shared__ float ms[HKC];
    __shared__ float mq[HKC];
    __shared__ float sc[KCLS];
    for (int i = tid; i < HKC; i += 256) { ms[i] = 0.f; mq[i] = 0.f; }
    if (tid < KCLS) sc[tid] = 0.f;
    __syncthreads();
    for (int ww = 0; ww < 8; ww++) {
        if (w == ww) {
#pragma unroll
            for (int j = 0; j < KCLS; j++) {
                ms[j * 32 + lane] += S[j];
                mq[j * 32 + lane] += Q[j];
            }
            if (lane < KCLS) sc[lane] += cntf;
        }
        __syncthreads();
    }
    float* s1p = g_s1p + (size_t)blockIdx.x * HKC;
    float* s2p = g_s2p + (size_t)blockIdx.x * HKC;
    for (int i = tid; i < HKC; i += 256) { s1p[i] = ms[i]; s2p[i] = mq[i]; }
    if (tid < KCLS) g_cntp[blockIdx.x * KCLS + tid] = sc[tid];
}

// ============================================================================
// Kernel 2: reduce partials -> (scale, shift); write style output tails.
// grid = 76 blocks (one per (b,k)), 64 threads (one per channel).
// Counts come from the half==0 slice only (both halves saw the same pixels).
// ============================================================================
__global__ void finalize_kernel(
    const float* __restrict__ style_means, const float* __restrict__ style_stds,
    float* __restrict__ dout)
{
    const int bk = blockIdx.x;            // 0..75
    const int c  = threadIdx.x;           // 0..63
    const int b  = bk / KCLS;
    const int k  = bk % KCLS;
    const int half  = c >> 5;
    const int lanec = c & 31;

    const int gbase  = (b * 2 + half) * BLKS_PER_SLICE;  // this channel's slice
    const int g0base = (b * 2) * BLKS_PER_SLICE;         // counts slice

    float s1 = 0.f, s2 = 0.f, cnt = 0.f;
    for (int blk = 0; blk < BLKS_PER_SLICE; blk++) {
        size_t g = (size_t)(gbase + blk) * HKC + k * 32 + lanec;
        s1  += g_s1p[g];
        s2  += g_s2p[g];
        cnt += g_cntp[(g0base + blk) * KCLS + k];
    }
    float cs   = fmaxf(cnt, 1.f);
    float mean = s1 / cs;
    float var  = (s2 - cs * mean * mean) / fmaxf(cnt - 1.f, 1.f);
    float stdc = sqrtf(fmaxf(var, 0.f)) + EPSf;
    bool valid = cnt > COUNTf;

    float sm = style_means[k * 64 + c];
    float ss = style_stds[k * 64 + c];
    float scale = valid ? (ss / stdc) : 1.f;
    float shift = valid ? (sm - mean * scale) : 0.f;
    g_comb[bk * 64 + c] = make_float2(scale, shift);

    // output tails: style_means_1dim | style_stds_1dim | valid_bk
    float* o1 = dout + (size_t)Bn * Cn * HWn;
    float* o2 = o1 + Bn * KCLS * Cn;
    float* o3 = o2 + Bn * KCLS * Cn;
    o1[bk * 64 + c] = valid ? sm : 0.f;
    o2[bk * 64 + c] = valid ? ss : 0.f;
    if (c == 0) o3[bk] = valid ? 1.f : 0.f;
}

// ============================================================================
// Kernel 3: apply. out = x * scale[b,lab,c] + shift[b,lab,c].
// Labels held in registers across the channel loop; (scale,shift) float2 table
// in SMEM with stride-67 padding (conflict-free label-indexed LDS.64).
// Pure float4 streaming otherwise.
// ============================================================================
__global__ __launch_bounds__(256) void apply_kernel(
    const float* __restrict__ x, const int* __restrict__ y,
    float* __restrict__ out)
{
    __shared__ float2 comb[KCLS * 67];

    const int tid = threadIdx.x;
    const int b   = blockIdx.x / (HWn / TA);
    const int tIn = blockIdx.x % (HWn / TA);
    const int p0  = tIn * TA;

    for (int i = tid; i < KCLS * Cn; i += 256) {
        int k = i >> 6, c = i & 63;
        comb[k * 67 + c] = g_comb[(b * KCLS + k) * 64 + c];
    }
    int4 lb = ((const int4*)(y + (size_t)b * HWn + p0))[tid];
    __syncthreads();

    const float* xb = x + (size_t)b * Cn * HWn + p0;
    float*       ob = out + (size_t)b * Cn * HWn + p0;

#pragma unroll 4
    for (int c = 0; c < Cn; c++) {
        float4 v = ((const float4*)(xb + (size_t)c * HWn))[tid];
        float2 t0 = comb[lb.x * 67 + c];
        float2 t1 = comb[lb.y * 67 + c];
        float2 t2 = comb[lb.z * 67 + c];
        float2 t3 = comb[lb.w * 67 + c];
        float4 r;
        r.x = fmaf(v.x, t0.x, t0.y);
        r.y = fmaf(v.y, t1.x, t1.y);
        r.z = fmaf(v.z, t2.x, t2.y);
        r.w = fmaf(v.w, t3.x, t3.y);
        ((float4*)(ob + (size_t)c * HWn))[tid] = r;
    }
}

// ============================================================================
extern "C" void kernel_launch(void* const* d_in, const int* in_sizes, int n_in,
                              void* d_out, int out_size)
{
    const float* x  = (const float*)d_in[0];   // x_content [4,64,512,512] f32
    const int*   y  = (const int*)d_in[1];     // y_content [4,512,512] i32
    const float* sm = (const float*)d_in[2];   // style_means [19,64] f32
    const float* ss = (const float*)d_in[3];   // style_stds  [19,64] f32
    float* out = (float*)d_out;

    stats_kernel<<<NBLK, 256>>>(x, y);
    finalize_kernel<<<Bn * KCLS, Cn>>>(sm, ss, out);
    apply_kernel<<<Bn * (HWn / TA), 256>>>(x, y, out);
}